// round 11
// baseline (speedup 1.0000x reference)
#include <cuda_runtime.h>
#include <cuda_fp16.h>

#define BATCH 8
#define LEN   2048
#define EMB   512
#define NQ    8
#define IT    16     // i-rows per attn block
#define JPT   4      // j-columns per thread
#define THR   512    // attn block size

#define ROT_GRID   296   // 148 SMs x 2 blocks
#define ROT_CHUNKS 512   // 16384 rows / 32 rows per chunk

// dynamic smem for the tanh buffer: (IT/2) pairs * THR * 16B = 64 KB
#define SMEM_TH_BYTES ((IT / 2) * THR * 16)

// scratch for rot = x @ rotation : (8, 2048, 8) fp32 = 512 KB (L2-resident)
__device__ float g_rot[BATCH * LEN * NQ];

__device__ __forceinline__ float tanh_fast(float x) {
    float y;
    asm("tanh.approx.f32 %0, %1;" : "=f"(y) : "f"(x));
    return y;
}
__device__ __forceinline__ unsigned int h2_to_u(__half2 h) {
    return *reinterpret_cast<unsigned int*>(&h);
}
__device__ __forceinline__ __half2 u_to_h2(unsigned int u) {
    return *reinterpret_cast<__half2*>(&u);
}

// ---------------------------------------------------------------------------
// Kernel 1: rot[b,l,q] = sum_e x[b,l,e] * rotation[e,q]
// Persistent grid (296 blocks x 256 thr), grid-stride over 512 chunks of 32
// rows: amortizes the 16 KB rotation preload + barrier, removes the partial-
// wave tail. Per chunk each warp computes 4 rows: 16 LDG.128 up-front
// (MLP=16), full 5-stage swap-butterfly -> lane l holds element (l>>3, l&7),
// one contiguous 128B STG per warp.
// ---------------------------------------------------------------------------
__global__ __launch_bounds__(256, 2) void rot_kernel(const float* __restrict__ x,
                                                     const float* __restrict__ rotation)
{
    __shared__ float4 srotT4[NQ][EMB / 4];   // transposed rotation, 16 KB
    const int tid = threadIdx.x;

    float* srot = reinterpret_cast<float*>(srotT4);
    for (int idx = tid; idx < EMB * NQ; idx += 256) {
        int e = idx >> 3;
        int q = idx & 7;
        srot[q * EMB + e] = rotation[idx];
    }
    __syncthreads();

    const int warp = tid >> 5;
    const int lane = tid & 31;

    for (int chunk = blockIdx.x; chunk < ROT_CHUNKS; chunk += gridDim.x) {
        const int row0 = (chunk * 8 + warp) * 4;   // 4 rows per warp

        // issue all 16 global loads first (4 rows x 4 chunks), MLP = 16
        float4 xv[4][4];
#pragma unroll
        for (int r = 0; r < 4; r++)
#pragma unroll
            for (int k = 0; k < 4; k++)
                xv[r][k] = reinterpret_cast<const float4*>(
                    x + (size_t)(row0 + r) * EMB)[k * 32 + lane];

        float a[32];   // a[o], o = r*8+q
#pragma unroll
        for (int o = 0; o < 32; o++) a[o] = 0.0f;

#pragma unroll
        for (int k = 0; k < 4; k++) {
#pragma unroll
            for (int q = 0; q < NQ; q++) {
                const float4 rq = srotT4[q][k * 32 + lane];
#pragma unroll
                for (int r = 0; r < 4; r++) {
                    float& acc = a[r * 8 + q];
                    acc = fmaf(xv[r][k].x, rq.x, acc);
                    acc = fmaf(xv[r][k].y, rq.y, acc);
                    acc = fmaf(xv[r][k].z, rq.z, acc);
                    acc = fmaf(xv[r][k].w, rq.w, acc);
                }
            }
        }

        // full swap-butterfly: after stages 16,8,4,2,1 lane l holds a[l] fully
        // reduced.
#pragma unroll
        for (int off = 16; off >= 1; off >>= 1) {
#pragma unroll
            for (int t = 0; t < 16; t++) {
                if (t < off) {
                    const bool hi = (lane & off) != 0;
                    const float give = hi ? a[t] : a[t + off];
                    const float keep = hi ? a[t + off] : a[t];
                    a[t] = keep + __shfl_xor_sync(0xffffffffu, give, off);
                }
            }
        }

        // lane l stores element (row = l>>3, q = l&7): contiguous 128B/warp
        g_rot[(size_t)row0 * NQ + lane] = a[0];
    }
}

// swap-butterfly reduce of 8 per-row partials within a warp.
// After: every lane holds the full-warp sum for row (lane & 7).
__device__ __forceinline__ void butterfly8(float a[8], int lane) {
#pragma unroll
    for (int off = 4; off >= 1; off >>= 1) {
#pragma unroll
        for (int t = 0; t < 4; t++) {
            if (t < off) {
                const bool hi = (lane & off) != 0;
                const float give = hi ? a[t] : a[t + off];
                const float keep = hi ? a[t + off] : a[t];
                a[t] = keep + __shfl_xor_sync(0xffffffffu, give, off);
            }
        }
    }
    a[0] += __shfl_xor_sync(0xffffffffu, a[0], 8);
    a[0] += __shfl_xor_sync(0xffffffffu, a[0], 16);
}

// ---------------------------------------------------------------------------
// Kernel 2: scores[b,i,j] = sigmoid(rot_i . rot_j) / row_sum
//   sigmoid(s) = 0.5 + 0.5*tanh(0.5*s)   (0.5 folded into qi)
//   row_sum    = 1024 + 0.5*sum_j tanh   ->  out = fmaf(t, h, h), h = 0.5/row_sum
// Block = 512 threads, IT=16, JPT=4, grid (128, 8). tanh buffer in 64 KB
// dynamic smem packed per i-PAIR as uint4 (8 STS.128 + 8 LDS.128 per thread,
// was 16+16 of 64-bit). Row-partial reduce in two 8-row batches (live a[8]).
// 64 regs -> 2 blocks/SM co-resident.
// ---------------------------------------------------------------------------
__global__ __launch_bounds__(THR, 2) void attn_kernel(float* __restrict__ out)
{
    extern __shared__ uint4 s_th[];     // [pair*THR + tid], pair = i>>1 (64 KB)
    __shared__ float s_q[IT * NQ];      // 0.5 * qi rows
    __shared__ float s_part[IT][16];
    __shared__ float s_h[IT];

    const int b    = blockIdx.y;
    const int i0   = blockIdx.x * IT;
    const int tid  = threadIdx.x;
    const int warp = tid >> 5;
    const int lane = tid & 31;

    if (tid < IT * NQ)
        s_q[tid] = 0.5f * g_rot[((size_t)b * LEN + i0) * NQ + tid];

    // this thread's 4 j-rows (128B contiguous): 8 x LDG.128, MLP = 8
    const float4* rj = reinterpret_cast<const float4*>(
        &g_rot[((size_t)b * LEN + tid * JPT) * NQ]);
    float4 v0[JPT], v1[JPT];
#pragma unroll
    for (int r = 0; r < JPT; r++) {
        v0[r] = __ldg(rj + r * 2 + 0);
        v1[r] = __ldg(rj + r * 2 + 1);
    }

    __syncthreads();

    const float4* sq4 = reinterpret_cast<const float4*>(s_q);
    float a[8];

#pragma unroll
    for (int half = 0; half < 2; half++) {
        unsigned int ue0 = 0, ue1 = 0;   // even-i tanh pair carry
#pragma unroll
        for (int u = 0; u < 8; u++) {
            const int i = half * 8 + u;
            const float4 q0 = sq4[i * 2 + 0];   // broadcast LDS.128
            const float4 q1 = sq4[i * 2 + 1];
            float t[JPT];
#pragma unroll
            for (int r = 0; r < JPT; r++) {
                float s0 = v0[r].x * q0.x;
                float s1 = v1[r].x * q1.x;
                s0 = fmaf(v0[r].y, q0.y, s0);
                s1 = fmaf(v1[r].y, q1.y, s1);
                s0 = fmaf(v0[r].z, q0.z, s0);
                s1 = fmaf(v1[r].z, q1.z, s1);
                s0 = fmaf(v0[r].w, q0.w, s0);
                s1 = fmaf(v1[r].w, q1.w, s1);
                t[r] = tanh_fast(s0 + s1);
            }
            a[u] = (t[0] + t[1]) + (t[2] + t[3]);
            const unsigned int ux = h2_to_u(__floats2half2_rn(t[0], t[1]));
            const unsigned int uy = h2_to_u(__floats2half2_rn(t[2], t[3]));
            if ((u & 1) == 0) {
                ue0 = ux; ue1 = uy;              // stash even i
            } else {
                uint4 u4;                        // pair (i-1, i) -> one STS.128
                u4.x = ue0; u4.y = ue1; u4.z = ux; u4.w = uy;
                s_th[(i >> 1) * THR + tid] = u4;
            }
        }
        butterfly8(a, lane);
        if (lane < 8)
            s_part[half * 8 + lane][warp] = a[0];
    }

    __syncthreads();

    // second level: warp w (16 warps) reduces row w's 16 warp-partials
    {
        float p = (lane < 16) ? s_part[warp][lane] : 0.0f;
#pragma unroll
        for (int off = 8; off >= 1; off >>= 1)
            p += __shfl_xor_sync(0xffffffffu, p, off);
        if (lane == 0)
            s_h[warp] = __fdividef(0.5f, fmaf(0.5f, p, 1024.0f));
    }
    __syncthreads();

    float4* obase = reinterpret_cast<float4*>(
        out + ((size_t)(b * LEN + i0)) * LEN) + tid;
#pragma unroll
    for (int pair = 0; pair < IT / 2; pair++) {
        const uint4 u4 = s_th[pair * THR + tid];   // LDS.128: two i-rows
        {
            const float h = s_h[pair * 2 + 0];
            const float2 lo = __half22float2(u_to_h2(u4.x));
            const float2 hi = __half22float2(u_to_h2(u4.y));
            float4 o;
            o.x = fmaf(lo.x, h, h);
            o.y = fmaf(lo.y, h, h);
            o.z = fmaf(hi.x, h, h);
            o.w = fmaf(hi.y, h, h);
            __stcs(obase, o);
            obase += LEN / 4;
        }
        {
            const float h = s_h[pair * 2 + 1];
            const float2 lo = __half22float2(u_to_h2(u4.z));
            const float2 hi = __half22float2(u_to_h2(u4.w));
            float4 o;
            o.x = fmaf(lo.x, h, h);
            o.y = fmaf(lo.y, h, h);
            o.z = fmaf(hi.x, h, h);
            o.w = fmaf(hi.y, h, h);
            __stcs(obase, o);
            obase += LEN / 4;
        }
    }
}

extern "C" void kernel_launch(void* const* d_in, const int* in_sizes, int n_in,
                              void* d_out, int out_size)
{
    const float* x        = (const float*)d_in[0];   // (8, 2048, 512)
    const float* rotation = (const float*)d_in[1];   // (512, 8)
    float* out = (float*)d_out;                      // (8, 2048, 2048)

    static int init = 0;
    if (!init) {
        cudaFuncSetAttribute(attn_kernel,
                             cudaFuncAttributeMaxDynamicSharedMemorySize,
                             SMEM_TH_BYTES);
        init = 1;
    }

    rot_kernel<<<ROT_GRID, 256>>>(x, rotation);

    dim3 grid(LEN / IT, BATCH);                      // (128, 8)
    attn_kernel<<<grid, THR, SMEM_TH_BYTES>>>(out);
}

// round 12
// speedup vs baseline: 1.2157x; 1.2157x over previous
#include <cuda_runtime.h>
#include <cuda_fp16.h>

#define BATCH 8
#define LEN   2048
#define EMB   512
#define NQ    8
#define IT    16     // i-rows per attn block
#define JPT   4      // j-columns per thread
#define THR   512    // attn block size

// dynamic smem for the tanh buffer: THR*IT*8 bytes = 64 KB
#define SMEM_TH_BYTES (THR * IT * 8)

// scratch for rot = x @ rotation : (8, 2048, 8) fp32 = 512 KB (L2-resident)
__device__ float g_rot[BATCH * LEN * NQ];

__device__ __forceinline__ unsigned int h2_to_u(__half2 h) {
    return *reinterpret_cast<unsigned int*>(&h);
}
__device__ __forceinline__ __half2 u_to_h2(unsigned int u) {
    return *reinterpret_cast<__half2*>(&u);
}
// packed half2 tanh: ONE MUFU op for two elements
__device__ __forceinline__ unsigned int tanh_h2(unsigned int s2) {
    unsigned int y;
    asm("tanh.approx.f16x2 %0, %1;" : "=r"(y) : "r"(s2));
    return y;
}

// ---------------------------------------------------------------------------
// Kernel 1: rot[b,l,q] = sum_e x[b,l,e] * rotation[e,q]
// 512 blocks x 256 threads (R10 form — persistent variant regressed in R11).
// Each warp computes 4 rows; 16 LDG.128 up-front (MLP=16). Full 5-stage
// swap-butterfly -> lane l holds element (l>>3, l&7): contiguous 128B
// STG per warp.
// ---------------------------------------------------------------------------
__global__ __launch_bounds__(256) void rot_kernel(const float* __restrict__ x,
                                                  const float* __restrict__ rotation)
{
    __shared__ float4 srotT4[NQ][EMB / 4];   // transposed rotation, 16 KB
    const int tid = threadIdx.x;

    float* srot = reinterpret_cast<float*>(srotT4);
    for (int idx = tid; idx < EMB * NQ; idx += 256) {
        int e = idx >> 3;
        int q = idx & 7;
        srot[q * EMB + e] = rotation[idx];
    }
    __syncthreads();

    const int warp = tid >> 5;
    const int lane = tid & 31;
    const int row0 = (blockIdx.x * 8 + warp) * 4;   // 4 rows per warp

    // issue all 16 global loads first (4 rows x 4 chunks), MLP = 16
    float4 xv[4][4];
#pragma unroll
    for (int r = 0; r < 4; r++)
#pragma unroll
        for (int k = 0; k < 4; k++)
            xv[r][k] = reinterpret_cast<const float4*>(
                x + (size_t)(row0 + r) * EMB)[k * 32 + lane];

    float a[32];   // a[o], o = r*8+q
#pragma unroll
    for (int o = 0; o < 32; o++) a[o] = 0.0f;

#pragma unroll
    for (int k = 0; k < 4; k++) {
#pragma unroll
        for (int q = 0; q < NQ; q++) {
            const float4 rq = srotT4[q][k * 32 + lane];
#pragma unroll
            for (int r = 0; r < 4; r++) {
                float& acc = a[r * 8 + q];
                acc = fmaf(xv[r][k].x, rq.x, acc);
                acc = fmaf(xv[r][k].y, rq.y, acc);
                acc = fmaf(xv[r][k].z, rq.z, acc);
                acc = fmaf(xv[r][k].w, rq.w, acc);
            }
        }
    }

    // full swap-butterfly: after stages 16,8,4,2,1 lane l holds a[l] reduced
#pragma unroll
    for (int off = 16; off >= 1; off >>= 1) {
#pragma unroll
        for (int t = 0; t < 16; t++) {
            if (t < off) {
                const bool hi = (lane & off) != 0;
                const float give = hi ? a[t] : a[t + off];
                const float keep = hi ? a[t + off] : a[t];
                a[t] = keep + __shfl_xor_sync(0xffffffffu, give, off);
            }
        }
    }

    g_rot[(size_t)row0 * NQ + lane] = a[0];
}

// swap-butterfly reduce of 8 per-row partials within a warp.
// After: every lane holds the full-warp sum for row (lane & 7).
__device__ __forceinline__ void butterfly8(float a[8], int lane) {
#pragma unroll
    for (int off = 4; off >= 1; off >>= 1) {
#pragma unroll
        for (int t = 0; t < 4; t++) {
            if (t < off) {
                const bool hi = (lane & off) != 0;
                const float give = hi ? a[t] : a[t + off];
                const float keep = hi ? a[t + off] : a[t];
                a[t] = keep + __shfl_xor_sync(0xffffffffu, give, off);
            }
        }
    }
    a[0] += __shfl_xor_sync(0xffffffffu, a[0], 8);
    a[0] += __shfl_xor_sync(0xffffffffu, a[0], 16);
}

// ---------------------------------------------------------------------------
// Kernel 2: scores[b,i,j] = sigmoid(rot_i . rot_j) / row_sum
//   sigmoid(s) = 0.5 + 0.5*tanh(0.5*s)   (0.5 folded into qi)
//   row_sum    = 1024 + 0.5*sum_j tanh   ->  out = fmaf(t, h, h), h = 0.5/row_sum
// Block = 512 threads, IT=16, JPT=4, grid (128, 8). tanh computed with
// tanh.approx.f16x2 — one MUFU op per TWO elements (the kernel was ~72%
// MUFU-bound at f32 tanh). s packed fp32->half2 (saturating: +-inf -> +-1),
// row sums accumulated in fp32. tanh buffer (already half2) in 64 KB dynamic
// smem, uint2 per (i,thread). 2 blocks/SM.
// ---------------------------------------------------------------------------
__global__ __launch_bounds__(THR, 2) void attn_kernel(float* __restrict__ out)
{
    extern __shared__ uint2 s_th[];     // [i*THR + tid]  (64 KB)
    __shared__ float s_q[IT * NQ];      // 0.5 * qi rows
    __shared__ float s_part[IT][16];
    __shared__ float s_h[IT];

    const int b    = blockIdx.y;
    const int i0   = blockIdx.x * IT;
    const int tid  = threadIdx.x;
    const int warp = tid >> 5;
    const int lane = tid & 31;

    if (tid < IT * NQ)
        s_q[tid] = 0.5f * g_rot[((size_t)b * LEN + i0) * NQ + tid];

    // this thread's 4 j-rows (128B contiguous): 8 x LDG.128, MLP = 8
    const float4* rj = reinterpret_cast<const float4*>(
        &g_rot[((size_t)b * LEN + tid * JPT) * NQ]);
    float4 v0[JPT], v1[JPT];
#pragma unroll
    for (int r = 0; r < JPT; r++) {
        v0[r] = __ldg(rj + r * 2 + 0);
        v1[r] = __ldg(rj + r * 2 + 1);
    }

    __syncthreads();

    const float4* sq4 = reinterpret_cast<const float4*>(s_q);
    float a[8];

#pragma unroll
    for (int half = 0; half < 2; half++) {
#pragma unroll
        for (int u = 0; u < 8; u++) {
            const int i = half * 8 + u;
            const float4 q0 = sq4[i * 2 + 0];   // broadcast LDS.128
            const float4 q1 = sq4[i * 2 + 1];
            float s[JPT];
#pragma unroll
            for (int r = 0; r < JPT; r++) {
                float s0 = v0[r].x * q0.x;
                float s1 = v1[r].x * q1.x;
                s0 = fmaf(v0[r].y, q0.y, s0);
                s1 = fmaf(v1[r].y, q1.y, s1);
                s0 = fmaf(v0[r].z, q0.z, s0);
                s1 = fmaf(v1[r].z, q1.z, s1);
                s0 = fmaf(v0[r].w, q0.w, s0);
                s1 = fmaf(v1[r].w, q1.w, s1);
                s[r] = s0 + s1;
            }
            // pack s to half2 (saturating) and tanh two-at-a-time on MUFU
            const unsigned int th0 = tanh_h2(h2_to_u(__floats2half2_rn(s[0], s[1])));
            const unsigned int th1 = tanh_h2(h2_to_u(__floats2half2_rn(s[2], s[3])));
            const float2 f0 = __half22float2(u_to_h2(th0));
            const float2 f1 = __half22float2(u_to_h2(th1));
            a[u] = (f0.x + f0.y) + (f1.x + f1.y);
            uint2 u2;
            u2.x = th0;
            u2.y = th1;
            s_th[i * THR + tid] = u2;           // STS.64, conflict-free
        }
        butterfly8(a, lane);
        if (lane < 8)
            s_part[half * 8 + lane][warp] = a[0];
    }

    __syncthreads();

    // second level: warp w (16 warps) reduces row w's 16 warp-partials
    {
        float p = (lane < 16) ? s_part[warp][lane] : 0.0f;
#pragma unroll
        for (int off = 8; off >= 1; off >>= 1)
            p += __shfl_xor_sync(0xffffffffu, p, off);
        if (lane == 0)
            s_h[warp] = __fdividef(0.5f, fmaf(0.5f, p, 1024.0f));
    }
    __syncthreads();

    float4* obase = reinterpret_cast<float4*>(
        out + ((size_t)(b * LEN + i0)) * LEN) + tid;
#pragma unroll
    for (int i = 0; i < IT; i++) {
        const float h = s_h[i];
        const uint2 u2 = s_th[i * THR + tid];   // LDS.64, conflict-free
        const float2 lo = __half22float2(u_to_h2(u2.x));
        const float2 hi = __half22float2(u_to_h2(u2.y));
        float4 o;
        o.x = fmaf(lo.x, h, h);
        o.y = fmaf(lo.y, h, h);
        o.z = fmaf(hi.x, h, h);
        o.w = fmaf(hi.y, h, h);
        __stcs(obase, o);                       // evict-first streaming STG.128
        obase += LEN / 4;
    }
}

extern "C" void kernel_launch(void* const* d_in, const int* in_sizes, int n_in,
                              void* d_out, int out_size)
{
    const float* x        = (const float*)d_in[0];   // (8, 2048, 512)
    const float* rotation = (const float*)d_in[1];   // (512, 8)
    float* out = (float*)d_out;                      // (8, 2048, 2048)

    static int init = 0;
    if (!init) {
        cudaFuncSetAttribute(attn_kernel,
                             cudaFuncAttributeMaxDynamicSharedMemorySize,
                             SMEM_TH_BYTES);
        init = 1;
    }

    rot_kernel<<<512, 256>>>(x, rotation);

    dim3 grid(LEN / IT, BATCH);                      // (128, 8)
    attn_kernel<<<grid, THR, SMEM_TH_BYTES>>>(out);
}

// round 13
// speedup vs baseline: 1.2320x; 1.0134x over previous
#include <cuda_runtime.h>
#include <cuda_fp16.h>

#define BATCH 8
#define LEN   2048
#define EMB   512
#define NQ    8
#define IT    16     // i-rows per attn block
#define JPT   4      // j-columns per thread
#define THR   512    // attn block size

// dynamic smem for the tanh buffer: THR*IT*8 bytes = 64 KB
#define SMEM_TH_BYTES (THR * IT * 8)

// scratch for rot = x @ rotation : (8, 2048, 8) fp32 = 512 KB (L2-resident)
__device__ float g_rot[BATCH * LEN * NQ];

__device__ __forceinline__ float tanh_fast(float x) {
    float y;
    asm("tanh.approx.f32 %0, %1;" : "=f"(y) : "f"(x));
    return y;
}
__device__ __forceinline__ unsigned int h2_to_u(__half2 h) {
    return *reinterpret_cast<unsigned int*>(&h);
}
__device__ __forceinline__ __half2 u_to_h2(unsigned int u) {
    return *reinterpret_cast<__half2*>(&u);
}

// ---------------------------------------------------------------------------
// Kernel 1: rot[b,l,q] = sum_e x[b,l,e] * rotation[e,q]
// 512 blocks x 256 threads, 3 blocks/SM (software-pipelined k-chunks keep
// only cur+next xv live: ~80 regs vs ~104 when all 16 loads are held).
// Waves drop 1.73 -> 1.15. Each warp computes 4 rows; full 5-stage
// swap-butterfly -> lane l holds element (l>>3, l&7): contiguous 128B
// STG per warp.
// ---------------------------------------------------------------------------
__global__ __launch_bounds__(256, 3) void rot_kernel(const float* __restrict__ x,
                                                     const float* __restrict__ rotation)
{
    __shared__ float4 srotT4[NQ][EMB / 4];   // transposed rotation, 16 KB
    const int tid = threadIdx.x;

    float* srot = reinterpret_cast<float*>(srotT4);
    for (int idx = tid; idx < EMB * NQ; idx += 256) {
        int e = idx >> 3;
        int q = idx & 7;
        srot[q * EMB + e] = rotation[idx];
    }
    __syncthreads();

    const int warp = tid >> 5;
    const int lane = tid & 31;
    const int row0 = (blockIdx.x * 8 + warp) * 4;   // 4 rows per warp

    const float4* xr[4];
#pragma unroll
    for (int r = 0; r < 4; r++)
        xr[r] = reinterpret_cast<const float4*>(x + (size_t)(row0 + r) * EMB);

    // prologue: load chunk 0 (4 LDG.128)
    float4 xv[4];
#pragma unroll
    for (int r = 0; r < 4; r++)
        xv[r] = xr[r][lane];

    float a[32];   // a[o], o = r*8+q
#pragma unroll
    for (int o = 0; o < 32; o++) a[o] = 0.0f;

#pragma unroll
    for (int k = 0; k < 4; k++) {
        // prefetch next chunk while consuming this one
        float4 xn[4];
        if (k < 3) {
#pragma unroll
            for (int r = 0; r < 4; r++)
                xn[r] = xr[r][(k + 1) * 32 + lane];
        }
#pragma unroll
        for (int q = 0; q < NQ; q++) {
            const float4 rq = srotT4[q][k * 32 + lane];
#pragma unroll
            for (int r = 0; r < 4; r++) {
                float& acc = a[r * 8 + q];
                acc = fmaf(xv[r].x, rq.x, acc);
                acc = fmaf(xv[r].y, rq.y, acc);
                acc = fmaf(xv[r].z, rq.z, acc);
                acc = fmaf(xv[r].w, rq.w, acc);
            }
        }
        if (k < 3) {
#pragma unroll
            for (int r = 0; r < 4; r++)
                xv[r] = xn[r];
        }
    }

    // full swap-butterfly: after stages 16,8,4,2,1 lane l holds a[l] reduced
#pragma unroll
    for (int off = 16; off >= 1; off >>= 1) {
#pragma unroll
        for (int t = 0; t < 16; t++) {
            if (t < off) {
                const bool hi = (lane & off) != 0;
                const float give = hi ? a[t] : a[t + off];
                const float keep = hi ? a[t + off] : a[t];
                a[t] = keep + __shfl_xor_sync(0xffffffffu, give, off);
            }
        }
    }

    g_rot[(size_t)row0 * NQ + lane] = a[0];
}

// swap-butterfly reduce of 8 per-row partials within a warp.
// After: every lane holds the full-warp sum for row (lane & 7).
__device__ __forceinline__ void butterfly8(float a[8], int lane) {
#pragma unroll
    for (int off = 4; off >= 1; off >>= 1) {
#pragma unroll
        for (int t = 0; t < 4; t++) {
            if (t < off) {
                const bool hi = (lane & off) != 0;
                const float give = hi ? a[t] : a[t + off];
                const float keep = hi ? a[t + off] : a[t];
                a[t] = keep + __shfl_xor_sync(0xffffffffu, give, off);
            }
        }
    }
    a[0] += __shfl_xor_sync(0xffffffffu, a[0], 8);
    a[0] += __shfl_xor_sync(0xffffffffu, a[0], 16);
}

// ---------------------------------------------------------------------------
// Kernel 2: scores[b,i,j] = sigmoid(rot_i . rot_j) / row_sum   (R10 form)
//   sigmoid(s) = 0.5 + 0.5*tanh(0.5*s)   (0.5 folded into qi)
//   row_sum    = 1024 + 0.5*sum_j tanh   ->  out = fmaf(t, h, h), h = 0.5/row_sum
// Block = 512 threads, IT=16, JPT=4, grid (128, 8). fp32 tanh (f16x2 variant
// regressed in R12 — MUFU is not the binding pipe). tanh buffer in 64 KB
// dynamic smem, uint2 per (i,thread), conflict-free STS.64/LDS.64.
// 64 regs -> 2 blocks/SM co-resident.
// ---------------------------------------------------------------------------
__global__ __launch_bounds__(THR, 2) void attn_kernel(float* __restrict__ out)
{
    extern __shared__ uint2 s_th[];     // [i*THR + tid]  (64 KB)
    __shared__ float s_q[IT * NQ];      // 0.5 * qi rows
    __shared__ float s_part[IT][16];
    __shared__ float s_h[IT];

    const int b    = blockIdx.y;
    const int i0   = blockIdx.x * IT;
    const int tid  = threadIdx.x;
    const int warp = tid >> 5;
    const int lane = tid & 31;

    if (tid < IT * NQ)
        s_q[tid] = 0.5f * g_rot[((size_t)b * LEN + i0) * NQ + tid];

    // this thread's 4 j-rows (128B contiguous): 8 x LDG.128, MLP = 8
    const float4* rj = reinterpret_cast<const float4*>(
        &g_rot[((size_t)b * LEN + tid * JPT) * NQ]);
    float4 v0[JPT], v1[JPT];
#pragma unroll
    for (int r = 0; r < JPT; r++) {
        v0[r] = __ldg(rj + r * 2 + 0);
        v1[r] = __ldg(rj + r * 2 + 1);
    }

    __syncthreads();

    const float4* sq4 = reinterpret_cast<const float4*>(s_q);
    float a[8];

#pragma unroll
    for (int half = 0; half < 2; half++) {
#pragma unroll
        for (int u = 0; u < 8; u++) {
            const int i = half * 8 + u;
            const float4 q0 = sq4[i * 2 + 0];   // broadcast LDS.128
            const float4 q1 = sq4[i * 2 + 1];
            float t[JPT];
#pragma unroll
            for (int r = 0; r < JPT; r++) {
                float s0 = v0[r].x * q0.x;
                float s1 = v1[r].x * q1.x;
                s0 = fmaf(v0[r].y, q0.y, s0);
                s1 = fmaf(v1[r].y, q1.y, s1);
                s0 = fmaf(v0[r].z, q0.z, s0);
                s1 = fmaf(v1[r].z, q1.z, s1);
                s0 = fmaf(v0[r].w, q0.w, s0);
                s1 = fmaf(v1[r].w, q1.w, s1);
                t[r] = tanh_fast(s0 + s1);
            }
            a[u] = (t[0] + t[1]) + (t[2] + t[3]);
            uint2 u2;
            u2.x = h2_to_u(__floats2half2_rn(t[0], t[1]));
            u2.y = h2_to_u(__floats2half2_rn(t[2], t[3]));
            s_th[i * THR + tid] = u2;           // STS.64, conflict-free
        }
        butterfly8(a, lane);
        if (lane < 8)
            s_part[half * 8 + lane][warp] = a[0];
    }

    __syncthreads();

    // second level: warp w (16 warps) reduces row w's 16 warp-partials
    {
        float p = (lane < 16) ? s_part[warp][lane] : 0.0f;
#pragma unroll
        for (int off = 8; off >= 1; off >>= 1)
            p += __shfl_xor_sync(0xffffffffu, p, off);
        if (lane == 0)
            s_h[warp] = __fdividef(0.5f, fmaf(0.5f, p, 1024.0f));
    }
    __syncthreads();

    float4* obase = reinterpret_cast<float4*>(
        out + ((size_t)(b * LEN + i0)) * LEN) + tid;
#pragma unroll
    for (int i = 0; i < IT; i++) {
        const float h = s_h[i];
        const uint2 u2 = s_th[i * THR + tid];   // LDS.64, conflict-free
        const float2 lo = __half22float2(u_to_h2(u2.x));
        const float2 hi = __half22float2(u_to_h2(u2.y));
        float4 o;
        o.x = fmaf(lo.x, h, h);
        o.y = fmaf(lo.y, h, h);
        o.z = fmaf(hi.x, h, h);
        o.w = fmaf(hi.y, h, h);
        __stcs(obase, o);                       // evict-first streaming STG.128
        obase += LEN / 4;
    }
}

extern "C" void kernel_launch(void* const* d_in, const int* in_sizes, int n_in,
                              void* d_out, int out_size)
{
    const float* x        = (const float*)d_in[0];   // (8, 2048, 512)
    const float* rotation = (const float*)d_in[1];   // (512, 8)
    float* out = (float*)d_out;                      // (8, 2048, 2048)

    static int init = 0;
    if (!init) {
        cudaFuncSetAttribute(attn_kernel,
                             cudaFuncAttributeMaxDynamicSharedMemorySize,
                             SMEM_TH_BYTES);
        init = 1;
    }

    rot_kernel<<<512, 256>>>(x, rotation);

    dim3 grid(LEN / IT, BATCH);                      // (128, 8)
    attn_kernel<<<grid, THR, SMEM_TH_BYTES>>>(out);
}